// round 13
// baseline (speedup 1.0000x reference)
#include <cuda_runtime.h>
#include <cuda.h>
#include <cuda_fp16.h>
#include <cstdint>
#include <cstddef>
#include <math.h>

#define HID   4096
#define IDIM  14336
#define TOK   4096
#define GS    64
#define HSC   512.0f

// ---------------- scratch (static device globals; no allocation) ----------------
__device__ __align__(128) __half d_w13[(size_t)2 * IDIM * HID];  // [2*IDIM, HID], rows interleaved: 2i=w1_i, 2i+1=w3_i
__device__ __align__(128) __half d_w2h[(size_t)HID * IDIM];      // [HID, IDIM]
__device__ __align__(128) __half d_xh [(size_t)TOK * HID];       // [TOK, HID]
__device__ __align__(128) __half d_h  [(size_t)TOK * IDIM];      // [TOK, IDIM], scaled 1/HSC

// ---------------- dequant / convert ----------------
__global__ void k_dequant_w13(const int* __restrict__ q1, const float* __restrict__ s1, const float* __restrict__ z1,
                              const int* __restrict__ q3, const float* __restrict__ s3, const float* __restrict__ z3) {
    int idx = blockIdx.x * blockDim.x + threadIdx.x;
    const int total = (int)((size_t)IDIM * HID / 4);
    if (idx >= total) return;
    int e   = idx * 4;
    int row = e >> 12;
    int col = e & (HID - 1);
    int gi  = row * (HID / GS) + (col >> 6);

    int4 q = ((const int4*)q1)[idx];
    float sc = s1[gi], zp = z1[gi];
    __half2* o = (__half2*)(d_w13 + (size_t)(2 * row) * HID + col);       // w1 -> even rows
    o[0] = __floats2half2_rn(((float)q.x - zp) * sc, ((float)q.y - zp) * sc);
    o[1] = __floats2half2_rn(((float)q.z - zp) * sc, ((float)q.w - zp) * sc);

    q = ((const int4*)q3)[idx];
    sc = s3[gi]; zp = z3[gi];
    o = (__half2*)(d_w13 + (size_t)(2 * row + 1) * HID + col);            // w3 -> odd rows
    o[0] = __floats2half2_rn(((float)q.x - zp) * sc, ((float)q.y - zp) * sc);
    o[1] = __floats2half2_rn(((float)q.z - zp) * sc, ((float)q.w - zp) * sc);
}

__global__ void k_dequant_w2(const int* __restrict__ qw, const float* __restrict__ s, const float* __restrict__ z) {
    int idx = blockIdx.x * blockDim.x + threadIdx.x;
    const int total = (int)((size_t)HID * IDIM / 4);
    if (idx >= total) return;
    int e   = idx * 4;
    int row = e / IDIM;
    int col = e - row * IDIM;
    int gi  = row * (IDIM / GS) + (col >> 6);

    int4 q = ((const int4*)qw)[idx];
    float sc = s[gi], zp = z[gi];
    __half2* o = (__half2*)(d_w2h + (size_t)e);
    o[0] = __floats2half2_rn(((float)q.x - zp) * sc, ((float)q.y - zp) * sc);
    o[1] = __floats2half2_rn(((float)q.z - zp) * sc, ((float)q.w - zp) * sc);
}

__global__ void k_cvt_x(const float* __restrict__ x) {
    int idx = blockIdx.x * blockDim.x + threadIdx.x;
    const int total = TOK * HID / 4;
    if (idx >= total) return;
    float4 v = ((const float4*)x)[idx];
    __half2* o = (__half2*)(d_xh + (size_t)idx * 4);
    o[0] = __floats2half2_rn(v.x, v.y);
    o[1] = __floats2half2_rn(v.z, v.w);
}

// ---------------- PTX helpers ----------------
__device__ __forceinline__ uint32_t s2u(const void* p) {
    uint32_t a;
    asm("{ .reg .u64 t; cvta.to.shared.u64 t, %1; cvt.u32.u64 %0, t; }" : "=r"(a) : "l"(p));
    return a;
}
__device__ __forceinline__ void mbar_init(uint32_t mbar, uint32_t cnt) {
    asm volatile("mbarrier.init.shared.b64 [%0], %1;\n" :: "r"(mbar), "r"(cnt) : "memory");
}
__device__ __forceinline__ void mbar_wait(uint32_t mbar, uint32_t parity) {
    uint32_t done;
    do {
        asm volatile("{\n\t.reg .pred p;\n\t"
                     "mbarrier.try_wait.parity.acquire.cta.shared::cta.b64 p, [%1], %2, 0x989680;\n\t"
                     "selp.b32 %0, 1, 0, p;\n\t}"
                     : "=r"(done) : "r"(mbar), "r"(parity) : "memory");
    } while (!done);
}
__device__ __forceinline__ void mbar_wait_relaxed(uint32_t mbar, uint32_t parity) {
    uint32_t done;
    do {
        asm volatile("{\n\t.reg .pred p;\n\t"
                     "mbarrier.try_wait.parity.relaxed.cta.shared::cta.b64 p, [%1], %2, 0x989680;\n\t"
                     "selp.b32 %0, 1, 0, p;\n\t}"
                     : "=r"(done) : "r"(mbar), "r"(parity) : "memory");
    } while (!done);
}
__device__ __forceinline__ void mbar_arrive(uint32_t mbar) {
    asm volatile("mbarrier.arrive.shared.b64 _, [%0];" :: "r"(mbar) : "memory");
}
__device__ __forceinline__ void mbar_expect_tx(uint32_t mbar, uint32_t bytes) {
    asm volatile("mbarrier.arrive.expect_tx.shared.b64 _, [%0], %1;" :: "r"(mbar), "r"(bytes) : "memory");
}
__device__ __forceinline__ void tma_load_2d(uint32_t dst, const CUtensorMap* tm, int x, int y, uint32_t mbar) {
    asm volatile("cp.async.bulk.tensor.2d.shared::cta.global.tile.mbarrier::complete_tx::bytes "
                 "[%0], [%1, {%2, %3}], [%4];"
                 :: "r"(dst), "l"(tm), "r"(x), "r"(y), "r"(mbar) : "memory");
}
__device__ __forceinline__ void ldsm4(uint32_t* r, uint32_t addr) {
    asm volatile("ldmatrix.sync.aligned.m8n8.x4.shared.b16 {%0,%1,%2,%3}, [%4];"
                 : "=r"(r[0]), "=r"(r[1]), "=r"(r[2]), "=r"(r[3]) : "r"(addr));
}
__device__ __forceinline__ void mma_16816(float* c, const uint32_t* a, const uint32_t* b) {
    asm volatile(
        "mma.sync.aligned.m16n8k16.row.col.f32.f16.f16.f32 "
        "{%0,%1,%2,%3}, {%4,%5,%6,%7}, {%8,%9}, {%0,%1,%2,%3};\n"
        : "+f"(c[0]), "+f"(c[1]), "+f"(c[2]), "+f"(c[3])
        : "r"(a[0]), "r"(a[1]), "r"(a[2]), "r"(a[3]), "r"(b[0]), "r"(b[1]));
}

// ---------------- persistent fp16 mma.sync NT GEMM, TMA + mbarrier pipeline ----------------
// Persistent CTAs loop over 128x128 output tiles (t = bid; t += gridDim, M-fastest).
// Per tile: 8 warps (2x4) of 64x32 warp tiles, BK=64 k-steps, 3-stage TMA ring whose
// stage cursors run CONTINUOUSLY across tiles (epilogue overlaps next tile's prefetch).
// SW128-swizzled SMEM, fragment double-buffering, early stage release, no mainloop barrier.
// C[M,N] = A[M,K] * B[N,K]^T ; A,B fp16 row-major K-contiguous.
// EPI=0: SwiGLU-fused epilogue — (g,u) column pairs -> fp16 h[M, N/2] scaled 1/HSC.
// EPI=1: fp32 output scaled by HSC.
template <int EPI>
__global__ void __launch_bounds__(256, 2) k_gemm_tma(const __grid_constant__ CUtensorMap tmA,
                                                     const __grid_constant__ CUtensorMap tmB,
                                                     void* __restrict__ Cv,
                                                     int N, int K, int ntm, int ntiles) {
    constexpr int BM = 128, BN = 128, BK = 64;
    constexpr int ROW_B = 128;                      // 64 halves, SW128 swizzled
    constexpr int A_BYTES = BM * ROW_B;             // 16384
    constexpr int STAGE_BYTES = (BM + BN) * ROW_B;  // 32768
    constexpr uint32_t STAGE_TX = STAGE_BYTES;

    extern __shared__ __align__(128) char smem[];
    const uint32_t raw = s2u(smem);
    const uint32_t sbase = (raw + 1023u) & ~1023u;  // SW128 atoms need 1024B alignment
    const uint32_t mb = sbase + 3 * STAGE_BYTES;    // full[s]=mb+16s, empty[s]=mb+16s+8

    const int tid  = threadIdx.x;
    const int warp = tid >> 5, lane = tid & 31;
    const int wm = warp >> 2, wn = warp & 3;        // 2x4 warp grid, warp tile 64x32
    const int KT = K / BK;
    const int G  = gridDim.x;
    const int nowned = (ntiles - (int)blockIdx.x + G - 1) / G;
    const long totalk = (long)nowned * KT;

    if (tid == 0) {
        asm volatile("prefetch.tensormap [%0];" :: "l"(&tmA));
        asm volatile("prefetch.tensormap [%0];" :: "l"(&tmB));
        for (int s = 0; s < 3; s++) {
            mbar_init(mb + s * 16, 1);      // full: expect_tx arrival
            mbar_init(mb + s * 16 + 8, 8);  // empty: 8 warp arrivals
        }
    }
    __syncthreads();

    // producer cursor (tid 0 only): linear k-step p -> (tile tj, kt)
    int pst = 0, pph = 1;
    auto produce = [&](long p) {
        int tj = (int)(p / KT), kt = (int)(p - (long)tj * KT);
        int t  = blockIdx.x + tj * G;
        int tbm = (t % ntm) * BM, tbn = (t / ntm) * BN;
        mbar_wait_relaxed(mb + pst * 16 + 8, pph);  // wait empty (async-proxy writes follow)
        mbar_expect_tx(mb + pst * 16, STAGE_TX);
        const uint32_t st = sbase + pst * STAGE_BYTES;
        tma_load_2d(st,           &tmA, kt * BK, tbm, mb + pst * 16);
        tma_load_2d(st + A_BYTES, &tmB, kt * BK, tbn, mb + pst * 16);
        if (++pst == 3) { pst = 0; pph ^= 1; }
    };
    if (tid == 0) { produce(0); if (totalk > 1) produce(1); }
    long pnext = 2;

    // consumer ldmatrix addressing (SW128: phys_chunk = chunk ^ (row & 7))
    const int xr = lane & 7;
    const int a_hi = lane >> 4;                     // 0/1 -> +8 halves in K
    const int b_hi = (lane >> 3) & 1;
    const uint32_t a_row = (uint32_t)(wm * 64 + (lane & 15)) * ROW_B;
    const uint32_t b_row = (uint32_t)A_BYTES +
                           (uint32_t)(wn * 32 + (lane & 7) + ((lane >> 4) & 1) * 8) * ROW_B;

    float acc[4][4][4];
    uint32_t af[2][4][4], bf[2][4][2];
    auto load_frags = [&](int buf, uint32_t st, int ks) {
        const uint32_t qa = (uint32_t)(((2 * ks + a_hi) ^ xr) * 16);
        const uint32_t a0 = st + a_row + qa;
#pragma unroll
        for (int mi = 0; mi < 4; mi++)
            ldsm4(af[buf][mi], a0 + mi * (16 * ROW_B));
        const uint32_t qb = (uint32_t)(((2 * ks + b_hi) ^ xr) * 16);
        const uint32_t b0 = st + b_row + qb;
        ldsm4(&bf[buf][0][0], b0);
        ldsm4(&bf[buf][2][0], b0 + 16 * ROW_B);
    };
    auto do_mma = [&](int buf) {
#pragma unroll
        for (int mi = 0; mi < 4; mi++)
#pragma unroll
            for (int ni = 0; ni < 4; ni++)
                mma_16816(acc[mi][ni], af[buf][mi], bf[buf][ni]);
    };

    // consumer cursors: ws/wph = full-wait parity cursor, cs = current stage
    int ws = 0, wph = 0, cs = 0;

#pragma unroll 1
    for (int tj = 0; tj < nowned; tj++) {
        const int t  = blockIdx.x + tj * G;
        const int bm = (t % ntm) * BM, bn = (t / ntm) * BN;

#pragma unroll
        for (int a = 0; a < 4; a++)
#pragma unroll
            for (int b = 0; b < 4; b++)
#pragma unroll
                for (int c = 0; c < 4; c++) acc[a][b][c] = 0.0f;

        mbar_wait(mb + ws * 16, wph);               // this tile's first stage full
        if (++ws == 3) { ws = 0; wph ^= 1; }
        load_frags(0, sbase + cs * STAGE_BYTES, 0);

#pragma unroll 1
        for (int kt = 0; kt < KT; kt++) {
            const uint32_t st = sbase + cs * STAGE_BYTES;
            load_frags(1, st, 1);
            do_mma(0);                              // ks0
            if (tid == 0 && pnext < totalk) { produce(pnext); pnext++; }
            load_frags(0, st, 2);
            do_mma(1);                              // ks1
            load_frags(1, st, 3);                   // LAST read of stage cs
            if (lane == 0) mbar_arrive(mb + cs * 16 + 8);  // EARLY release
            do_mma(0);                              // ks2
            if (kt + 1 < KT) {
                mbar_wait(mb + ws * 16, wph);       // next stage full
                if (++ws == 3) { ws = 0; wph ^= 1; }
                load_frags(0, sbase + ((cs + 1) % 3) * STAGE_BYTES, 0);
            }
            do_mma(1);                              // ks3
            cs = (cs + 1) % 3;
        }

        // ---------------- per-tile epilogue ----------------
#pragma unroll
        for (int mi = 0; mi < 4; mi++) {
#pragma unroll
            for (int ni = 0; ni < 4; ni++) {
                const int row = bm + wm * 64 + mi * 16 + (lane >> 2);
                const int col = bn + wn * 32 + ni * 8 + (lane & 3) * 2;
                if constexpr (EPI == 0) {
                    __half* C = (__half*)Cv;
                    const int No = N >> 1;
                    float g0 = acc[mi][ni][0], u0 = acc[mi][ni][1];
                    float g1 = acc[mi][ni][2], u1 = acc[mi][ni][3];
                    float h0 = __fdividef(g0, 1.0f + __expf(-g0)) * u0 * (1.0f / HSC);
                    float h1 = __fdividef(g1, 1.0f + __expf(-g1)) * u1 * (1.0f / HSC);
                    C[(size_t)row * No + (col >> 1)]       = __float2half_rn(h0);
                    C[(size_t)(row + 8) * No + (col >> 1)] = __float2half_rn(h1);
                } else {
                    float* C = (float*)Cv;
                    float2 v0 = make_float2(acc[mi][ni][0] * HSC, acc[mi][ni][1] * HSC);
                    float2 v1 = make_float2(acc[mi][ni][2] * HSC, acc[mi][ni][3] * HSC);
                    *(float2*)(C + (size_t)row * N + col)       = v0;
                    *(float2*)(C + (size_t)(row + 8) * N + col) = v1;
                }
            }
        }
    }
}

// ---------------- host: tensormap creation via driver entry point ----------------
typedef CUresult (CUDAAPI *PFN_TMEncode)(
    CUtensorMap*, CUtensorMapDataType, cuuint32_t, void*,
    const cuuint64_t*, const cuuint64_t*, const cuuint32_t*, const cuuint32_t*,
    CUtensorMapInterleave, CUtensorMapSwizzle, CUtensorMapL2promotion, CUtensorMapFloatOOBfill);

static void make_map_f16(PFN_TMEncode enc, CUtensorMap* tm, void* ptr,
                         unsigned long long inner, unsigned long long rows) {
    cuuint64_t dims[2]    = {inner, rows};
    cuuint64_t strides[1] = {inner * 2};          // bytes
    cuuint32_t box[2]     = {64, 128};            // 128B inner (SW128 limit), 128 rows
    cuuint32_t es[2]      = {1, 1};
    enc(tm, CU_TENSOR_MAP_DATA_TYPE_FLOAT16, 2, ptr, dims, strides, box, es,
        CU_TENSOR_MAP_INTERLEAVE_NONE, CU_TENSOR_MAP_SWIZZLE_128B,
        CU_TENSOR_MAP_L2_PROMOTION_L2_128B, CU_TENSOR_MAP_FLOAT_OOB_FILL_NONE);
}

// ---------------- launch ----------------
extern "C" void kernel_launch(void* const* d_in, const int* in_sizes, int n_in,
                              void* d_out, int out_size) {
    const float* x   = (const float*)d_in[0];
    const int*   w1q = (const int*)  d_in[1];
    const float* w1s = (const float*)d_in[2];
    const float* w1z = (const float*)d_in[3];
    const int*   w3q = (const int*)  d_in[4];
    const float* w3s = (const float*)d_in[5];
    const float* w3z = (const float*)d_in[6];
    const int*   w2q = (const int*)  d_in[7];
    const float* w2s = (const float*)d_in[8];
    const float* w2z = (const float*)d_in[9];
    float* out = (float*)d_out;

    __half *p_w13, *p_w2h, *p_xh, *p_h;
    cudaGetSymbolAddress((void**)&p_w13, d_w13);
    cudaGetSymbolAddress((void**)&p_w2h, d_w2h);
    cudaGetSymbolAddress((void**)&p_xh,  d_xh);
    cudaGetSymbolAddress((void**)&p_h,   d_h);

    void* fn = nullptr;
    cudaDriverEntryPointQueryResult qres;
    cudaGetDriverEntryPoint("cuTensorMapEncodeTiled", &fn, cudaEnableDefault, &qres);
    PFN_TMEncode enc = (PFN_TMEncode)fn;

    CUtensorMap tmX, tmW13, tmH, tmW2;
    make_map_f16(enc, &tmX,   p_xh,  HID,  TOK);        // A of GEMM1
    make_map_f16(enc, &tmW13, p_w13, HID,  2 * IDIM);   // B of GEMM1
    make_map_f16(enc, &tmH,   p_h,   IDIM, TOK);        // A of GEMM2
    make_map_f16(enc, &tmW2,  p_w2h, IDIM, HID);        // B of GEMM2

    const int SMEM = 1024 + 3 * 32768 + 128;   // align slack + 3 stages + mbarriers
    cudaFuncSetAttribute(k_gemm_tma<0>, cudaFuncAttributeMaxDynamicSharedMemorySize, SMEM);
    cudaFuncSetAttribute(k_gemm_tma<1>, cudaFuncAttributeMaxDynamicSharedMemorySize, SMEM);

    int sms = 0;
    cudaDeviceGetAttribute(&sms, cudaDevAttrMultiProcessorCount, 0);
    const int G1t = (TOK / 128) * ((2 * IDIM) / 128);   // 7168 tiles
    const int G2t = (TOK / 128) * (HID / 128);          // 1024 tiles
    int G = sms * 2;
    int G1 = G < G1t ? G : G1t;
    int G2 = G < G2t ? G : G2t;

    const int tqw13 = (int)((size_t)IDIM * HID / 4);
    k_dequant_w13<<<(tqw13 + 255) / 256, 256>>>(w1q, w1s, w1z, w3q, w3s, w3z);

    const int tqw2 = (int)((size_t)HID * IDIM / 4);
    k_dequant_w2<<<(tqw2 + 255) / 256, 256>>>(w2q, w2s, w2z);

    const int tx = TOK * HID / 4;
    k_cvt_x<<<(tx + 255) / 256, 256>>>(x);

    // h = silu(x w1^T) * (x w3^T), fused: N = 2*IDIM interleaved -> h [TOK, IDIM]
    k_gemm_tma<0><<<G1, 256, SMEM>>>(tmX, tmW13, p_h, 2 * IDIM, HID, TOK / 128, G1t);

    // out = h * w2^T (x HSC) -> fp32 [TOK, HID]
    k_gemm_tma<1><<<G2, 256, SMEM>>>(tmH, tmW2, out, HID, IDIM, TOK / 128, G2t);
}

// round 14
// speedup vs baseline: 1.2476x; 1.2476x over previous
#include <cuda_runtime.h>
#include <cuda.h>
#include <cuda_fp16.h>
#include <cstdint>
#include <cstddef>
#include <math.h>

#define HID   4096
#define IDIM  14336
#define TOK   4096
#define GS    64
#define HSC   512.0f

// ---------------- scratch (static device globals; no allocation) ----------------
__device__ __align__(128) __half d_w13[(size_t)2 * IDIM * HID];  // [2*IDIM, HID], rows interleaved: 2i=w1_i, 2i+1=w3_i
__device__ __align__(128) __half d_w2h[(size_t)HID * IDIM];      // [HID, IDIM]
__device__ __align__(128) __half d_xh [(size_t)TOK * HID];       // [TOK, HID]
__device__ __align__(128) __half d_h  [(size_t)TOK * IDIM];      // [TOK, IDIM], scaled 1/HSC

// ---------------- fused prep: dequant w13 + dequant w2 + cvt x ----------------
__global__ void k_prep(const float* __restrict__ x,
                       const int* __restrict__ q1, const float* __restrict__ s1, const float* __restrict__ z1,
                       const int* __restrict__ q3, const float* __restrict__ s3, const float* __restrict__ z3,
                       const int* __restrict__ q2, const float* __restrict__ s2, const float* __restrict__ z2) {
    const int T13 = (int)((size_t)IDIM * HID / 4);   // 14,680,064
    const int T2  = (int)((size_t)HID * IDIM / 4);   // 14,680,064
    int idx = blockIdx.x * blockDim.x + threadIdx.x;

    if (idx < T13) {
        int e   = idx * 4;
        int row = e >> 12;
        int col = e & (HID - 1);
        int gi  = row * (HID / GS) + (col >> 6);

        int4 q = ((const int4*)q1)[idx];
        float sc = s1[gi], zp = z1[gi];
        __half2* o = (__half2*)(d_w13 + (size_t)(2 * row) * HID + col);       // w1 -> even rows
        o[0] = __floats2half2_rn(((float)q.x - zp) * sc, ((float)q.y - zp) * sc);
        o[1] = __floats2half2_rn(((float)q.z - zp) * sc, ((float)q.w - zp) * sc);

        q = ((const int4*)q3)[idx];
        sc = s3[gi]; zp = z3[gi];
        o = (__half2*)(d_w13 + (size_t)(2 * row + 1) * HID + col);            // w3 -> odd rows
        o[0] = __floats2half2_rn(((float)q.x - zp) * sc, ((float)q.y - zp) * sc);
        o[1] = __floats2half2_rn(((float)q.z - zp) * sc, ((float)q.w - zp) * sc);
    } else if (idx < T13 + T2) {
        idx -= T13;
        int e   = idx * 4;
        int row = e / IDIM;
        int col = e - row * IDIM;
        int gi  = row * (IDIM / GS) + (col >> 6);

        int4 q = ((const int4*)q2)[idx];
        float sc = s2[gi], zp = z2[gi];
        __half2* o = (__half2*)(d_w2h + (size_t)e);
        o[0] = __floats2half2_rn(((float)q.x - zp) * sc, ((float)q.y - zp) * sc);
        o[1] = __floats2half2_rn(((float)q.z - zp) * sc, ((float)q.w - zp) * sc);
    } else {
        idx -= T13 + T2;
        if (idx < TOK * HID / 4) {
            float4 v = ((const float4*)x)[idx];
            __half2* o = (__half2*)(d_xh + (size_t)idx * 4);
            o[0] = __floats2half2_rn(v.x, v.y);
            o[1] = __floats2half2_rn(v.z, v.w);
        }
    }
}

// ---------------- PTX helpers ----------------
__device__ __forceinline__ uint32_t s2u(const void* p) {
    uint32_t a;
    asm("{ .reg .u64 t; cvta.to.shared.u64 t, %1; cvt.u32.u64 %0, t; }" : "=r"(a) : "l"(p));
    return a;
}
__device__ __forceinline__ void mbar_init(uint32_t mbar, uint32_t cnt) {
    asm volatile("mbarrier.init.shared.b64 [%0], %1;\n" :: "r"(mbar), "r"(cnt) : "memory");
}
__device__ __forceinline__ void mbar_wait(uint32_t mbar, uint32_t parity) {
    uint32_t done;
    do {
        asm volatile("{\n\t.reg .pred p;\n\t"
                     "mbarrier.try_wait.parity.acquire.cta.shared::cta.b64 p, [%1], %2, 0x989680;\n\t"
                     "selp.b32 %0, 1, 0, p;\n\t}"
                     : "=r"(done) : "r"(mbar), "r"(parity) : "memory");
    } while (!done);
}
__device__ __forceinline__ void mbar_wait_relaxed(uint32_t mbar, uint32_t parity) {
    uint32_t done;
    do {
        asm volatile("{\n\t.reg .pred p;\n\t"
                     "mbarrier.try_wait.parity.relaxed.cta.shared::cta.b64 p, [%1], %2, 0x989680;\n\t"
                     "selp.b32 %0, 1, 0, p;\n\t}"
                     : "=r"(done) : "r"(mbar), "r"(parity) : "memory");
    } while (!done);
}
__device__ __forceinline__ void mbar_arrive(uint32_t mbar) {
    asm volatile("mbarrier.arrive.shared.b64 _, [%0];" :: "r"(mbar) : "memory");
}
__device__ __forceinline__ void mbar_expect_tx(uint32_t mbar, uint32_t bytes) {
    asm volatile("mbarrier.arrive.expect_tx.shared.b64 _, [%0], %1;" :: "r"(mbar), "r"(bytes) : "memory");
}
__device__ __forceinline__ void tma_load_2d(uint32_t dst, const CUtensorMap* tm, int x, int y, uint32_t mbar) {
    asm volatile("cp.async.bulk.tensor.2d.shared::cta.global.tile.mbarrier::complete_tx::bytes "
                 "[%0], [%1, {%2, %3}], [%4];"
                 :: "r"(dst), "l"(tm), "r"(x), "r"(y), "r"(mbar) : "memory");
}
__device__ __forceinline__ void ldsm4(uint32_t* r, uint32_t addr) {
    asm volatile("ldmatrix.sync.aligned.m8n8.x4.shared.b16 {%0,%1,%2,%3}, [%4];"
                 : "=r"(r[0]), "=r"(r[1]), "=r"(r[2]), "=r"(r[3]) : "r"(addr));
}
__device__ __forceinline__ void mma_16816(float* c, const uint32_t* a, const uint32_t* b) {
    asm volatile(
        "mma.sync.aligned.m16n8k16.row.col.f32.f16.f16.f32 "
        "{%0,%1,%2,%3}, {%4,%5,%6,%7}, {%8,%9}, {%0,%1,%2,%3};\n"
        : "+f"(c[0]), "+f"(c[1]), "+f"(c[2]), "+f"(c[3])
        : "r"(a[0]), "r"(a[1]), "r"(a[2]), "r"(a[3]), "r"(b[0]), "r"(b[1]));
}
__device__ __forceinline__ void sts16(uint32_t addr, uint16_t v) {
    asm volatile("st.shared.u16 [%0], %1;" :: "r"(addr), "h"(v) : "memory");
}
__device__ __forceinline__ void lds128(uint32_t addr, uint32_t* v) {
    asm volatile("ld.shared.v4.u32 {%0,%1,%2,%3}, [%4];"
                 : "=r"(v[0]), "=r"(v[1]), "=r"(v[2]), "=r"(v[3]) : "r"(addr));
}

// ---------------- fp16 mma.sync NT GEMM, TMA + mbarrier pipeline ----------------
// 128x128x64 CTA k-tile, 8 warps (2x4) of 64x32 warp tiles, 3-stage TMA ring,
// SW128-swizzled SMEM, fragment double-buffering, early stage release,
// no mainloop __syncthreads.  (R10 structure — best measured.)
// C[M,N] = A[M,K] * B[N,K]^T ; A,B fp16 row-major K-contiguous.
// EPI=0: SwiGLU-fused epilogue, smem-staged coalesced fp16 stores of h[M, N/2] (1/HSC).
// EPI=1: fp32 output scaled by HSC, direct stores.
template <int EPI>
__global__ void __launch_bounds__(256, 2) k_gemm_tma(const __grid_constant__ CUtensorMap tmA,
                                                     const __grid_constant__ CUtensorMap tmB,
                                                     void* __restrict__ Cv,
                                                     int N, int K) {
    constexpr int BM = 128, BN = 128, BK = 64;
    constexpr int ROW_B = 128;                      // 64 halves, SW128 swizzled
    constexpr int A_BYTES = BM * ROW_B;             // 16384
    constexpr int STAGE_BYTES = (BM + BN) * ROW_B;  // 32768
    constexpr uint32_t STAGE_TX = STAGE_BYTES;
    constexpr int EPI_STRIDE_H = 72;                // padded half-stride for epilogue staging

    extern __shared__ __align__(128) char smem[];
    const uint32_t raw = s2u(smem);
    const uint32_t sbase = (raw + 1023u) & ~1023u;  // SW128 atoms need 1024B alignment
    const uint32_t mb = sbase + 3 * STAGE_BYTES;    // full[s]=mb+16s, empty[s]=mb+16s+8

    const int tid  = threadIdx.x;
    const int warp = tid >> 5, lane = tid & 31;
    const int wm = warp >> 2, wn = warp & 3;        // 2x4 warp grid, warp tile 64x32
    const int bm = blockIdx.x * BM, bn = blockIdx.y * BN;
    const int KT = K / BK;

    if (tid == 0) {
        asm volatile("prefetch.tensormap [%0];" :: "l"(&tmA));
        asm volatile("prefetch.tensormap [%0];" :: "l"(&tmB));
        for (int s = 0; s < 3; s++) {
            mbar_init(mb + s * 16, 1);      // full: expect_tx arrival
            mbar_init(mb + s * 16 + 8, 8);  // empty: 8 warp arrivals
        }
    }
    __syncthreads();

    float acc[4][4][4];
#pragma unroll
    for (int a = 0; a < 4; a++)
#pragma unroll
        for (int b = 0; b < 4; b++)
#pragma unroll
            for (int c = 0; c < 4; c++) acc[a][b][c] = 0.0f;

    // producer cursor (tid 0 only): produce data index i into stage i%3
    int pst = 0, pph = 1;
    auto produce = [&](int i) {
        mbar_wait_relaxed(mb + pst * 16 + 8, pph);  // wait empty (async-proxy writes follow)
        mbar_expect_tx(mb + pst * 16, STAGE_TX);
        const uint32_t st = sbase + pst * STAGE_BYTES;
        tma_load_2d(st,           &tmA, i * BK, bm, mb + pst * 16);
        tma_load_2d(st + A_BYTES, &tmB, i * BK, bn, mb + pst * 16);
        if (++pst == 3) { pst = 0; pph ^= 1; }
    };
    if (tid == 0) { produce(0); produce(1); }

    // consumer ldmatrix addressing (SW128: phys_chunk = chunk ^ (row & 7))
    const int xr = lane & 7;
    const int a_hi = lane >> 4;                     // 0/1 -> +8 halves in K
    const int b_hi = (lane >> 3) & 1;
    const uint32_t a_row = (uint32_t)(wm * 64 + (lane & 15)) * ROW_B;
    const uint32_t b_row = (uint32_t)A_BYTES +
                           (uint32_t)(wn * 32 + (lane & 7) + ((lane >> 4) & 1) * 8) * ROW_B;

    uint32_t af[2][4][4], bf[2][4][2];
    auto load_frags = [&](int buf, uint32_t st, int ks) {
        const uint32_t qa = (uint32_t)(((2 * ks + a_hi) ^ xr) * 16);
        const uint32_t a0 = st + a_row + qa;
#pragma unroll
        for (int mi = 0; mi < 4; mi++)
            ldsm4(af[buf][mi], a0 + mi * (16 * ROW_B));
        const uint32_t qb = (uint32_t)(((2 * ks + b_hi) ^ xr) * 16);
        const uint32_t b0 = st + b_row + qb;
        ldsm4(&bf[buf][0][0], b0);
        ldsm4(&bf[buf][2][0], b0 + 16 * ROW_B);
    };
    auto do_mma = [&](int buf) {
#pragma unroll
        for (int mi = 0; mi < 4; mi++)
#pragma unroll
            for (int ni = 0; ni < 4; ni++)
                mma_16816(acc[mi][ni], af[buf][mi], bf[buf][ni]);
    };

    // consumer full-wait cursor
    int ws = 0, wph = 0;
    mbar_wait(mb + ws * 16, wph);                   // stage 0 full
    if (++ws == 3) { ws = 0; wph ^= 1; }
    load_frags(0, sbase, 0);

#pragma unroll 1
    for (int kt = 0; kt < KT; kt++) {
        const int s = kt % 3;
        const uint32_t st = sbase + s * STAGE_BYTES;
        load_frags(1, st, 1);
        do_mma(0);                                  // ks0
        if (tid == 0 && kt + 2 < KT) produce(kt + 2);
        load_frags(0, st, 2);
        do_mma(1);                                  // ks1
        load_frags(1, st, 3);                       // LAST read of stage s (per-warp smem order)
        if (lane == 0) mbar_arrive(mb + s * 16 + 8);  // EARLY release of stage s
        do_mma(0);                                  // ks2
        if (kt + 1 < KT) {
            mbar_wait(mb + ws * 16, wph);           // next stage full
            if (++ws == 3) { ws = 0; wph ^= 1; }
            load_frags(0, sbase + ((kt + 1) % 3) * STAGE_BYTES, 0);
        }
        do_mma(1);                                  // ks3
    }

    // ---------------- epilogue ----------------
    if constexpr (EPI == 0) {
        // SwiGLU + smem-staged coalesced stores.
        __syncthreads();                            // all warps done with stage smem
        const uint32_t eb = sbase;                  // 128 x 72 halves staging buffer
#pragma unroll
        for (int mi = 0; mi < 4; mi++) {
#pragma unroll
            for (int ni = 0; ni < 4; ni++) {
                const int r0 = wm * 64 + mi * 16 + (lane >> 2);     // local row 0..127
                const int c  = wn * 16 + ni * 4 + (lane & 3);       // local half-col 0..63
                float g0 = acc[mi][ni][0], u0 = acc[mi][ni][1];
                float g1 = acc[mi][ni][2], u1 = acc[mi][ni][3];
                float h0 = __fdividef(g0, 1.0f + __expf(-g0)) * u0 * (1.0f / HSC);
                float h1 = __fdividef(g1, 1.0f + __expf(-g1)) * u1 * (1.0f / HSC);
                sts16(eb + (uint32_t)(r0 * EPI_STRIDE_H + c) * 2,
                      __half_as_ushort(__float2half_rn(h0)));
                sts16(eb + (uint32_t)((r0 + 8) * EPI_STRIDE_H + c) * 2,
                      __half_as_ushort(__float2half_rn(h1)));
            }
        }
        __syncthreads();
        // coalesced copy: 128 rows x 64 halves (128B/row), 8 x 16B chunks per row
        __half* C = (__half*)Cv;
        const int No = N >> 1;
        const int rr = tid >> 3;                    // row 0..31 (+32 per iter)
        const int ch = tid & 7;                     // 16B chunk
#pragma unroll
        for (int it = 0; it < 4; it++) {
            const int r = rr + it * 32;
            uint32_t v[4];
            lds128(eb + (uint32_t)(r * EPI_STRIDE_H + ch * 8) * 2, v);
            *(uint4*)(C + (size_t)(bm + r) * No + (bn >> 1) + ch * 8) =
                make_uint4(v[0], v[1], v[2], v[3]);
        }
    } else {
#pragma unroll
        for (int mi = 0; mi < 4; mi++) {
#pragma unroll
            for (int ni = 0; ni < 4; ni++) {
                const int row = bm + wm * 64 + mi * 16 + (lane >> 2);
                const int col = bn + wn * 32 + ni * 8 + (lane & 3) * 2;
                float* C = (float*)Cv;
                float2 v0 = make_float2(acc[mi][ni][0] * HSC, acc[mi][ni][1] * HSC);
                float2 v1 = make_float2(acc[mi][ni][2] * HSC, acc[mi][ni][3] * HSC);
                *(float2*)(C + (size_t)row * N + col)       = v0;
                *(float2*)(C + (size_t)(row + 8) * N + col) = v1;
            }
        }
    }
}

// ---------------- host: tensormap creation via driver entry point ----------------
typedef CUresult (CUDAAPI *PFN_TMEncode)(
    CUtensorMap*, CUtensorMapDataType, cuuint32_t, void*,
    const cuuint64_t*, const cuuint64_t*, const cuuint32_t*, const cuuint32_t*,
    CUtensorMapInterleave, CUtensorMapSwizzle, CUtensorMapL2promotion, CUtensorMapFloatOOBfill);

static void make_map_f16(PFN_TMEncode enc, CUtensorMap* tm, void* ptr,
                         unsigned long long inner, unsigned long long rows) {
    cuuint64_t dims[2]    = {inner, rows};
    cuuint64_t strides[1] = {inner * 2};          // bytes
    cuuint32_t box[2]     = {64, 128};            // 128B inner (SW128 limit), 128 rows
    cuuint32_t es[2]      = {1, 1};
    enc(tm, CU_TENSOR_MAP_DATA_TYPE_FLOAT16, 2, ptr, dims, strides, box, es,
        CU_TENSOR_MAP_INTERLEAVE_NONE, CU_TENSOR_MAP_SWIZZLE_128B,
        CU_TENSOR_MAP_L2_PROMOTION_L2_128B, CU_TENSOR_MAP_FLOAT_OOB_FILL_NONE);
}

// ---------------- launch ----------------
extern "C" void kernel_launch(void* const* d_in, const int* in_sizes, int n_in,
                              void* d_out, int out_size) {
    const float* x   = (const float*)d_in[0];
    const int*   w1q = (const int*)  d_in[1];
    const float* w1s = (const float*)d_in[2];
    const float* w1z = (const float*)d_in[3];
    const int*   w3q = (const int*)  d_in[4];
    const float* w3s = (const float*)d_in[5];
    const float* w3z = (const float*)d_in[6];
    const int*   w2q = (const int*)  d_in[7];
    const float* w2s = (const float*)d_in[8];
    const float* w2z = (const float*)d_in[9];
    float* out = (float*)d_out;

    __half *p_w13, *p_w2h, *p_xh, *p_h;
    cudaGetSymbolAddress((void**)&p_w13, d_w13);
    cudaGetSymbolAddress((void**)&p_w2h, d_w2h);
    cudaGetSymbolAddress((void**)&p_xh,  d_xh);
    cudaGetSymbolAddress((void**)&p_h,   d_h);

    void* fn = nullptr;
    cudaDriverEntryPointQueryResult qres;
    cudaGetDriverEntryPoint("cuTensorMapEncodeTiled", &fn, cudaEnableDefault, &qres);
    PFN_TMEncode enc = (PFN_TMEncode)fn;

    CUtensorMap tmX, tmW13, tmH, tmW2;
    make_map_f16(enc, &tmX,   p_xh,  HID,  TOK);        // A of GEMM1
    make_map_f16(enc, &tmW13, p_w13, HID,  2 * IDIM);   // B of GEMM1
    make_map_f16(enc, &tmH,   p_h,   IDIM, TOK);        // A of GEMM2
    make_map_f16(enc, &tmW2,  p_w2h, IDIM, HID);        // B of GEMM2

    const int SMEM = 1024 + 3 * 32768 + 128;   // align slack + 3 stages + mbarriers
    cudaFuncSetAttribute(k_gemm_tma<0>, cudaFuncAttributeMaxDynamicSharedMemorySize, SMEM);
    cudaFuncSetAttribute(k_gemm_tma<1>, cudaFuncAttributeMaxDynamicSharedMemorySize, SMEM);

    // fused prep: w13 dequant + w2 dequant + x convert in one launch
    const long T13 = (long)IDIM * HID / 4;
    const long T2  = (long)HID * IDIM / 4;
    const long TX  = (long)TOK * HID / 4;
    const long TP  = T13 + T2 + TX;
    k_prep<<<(int)((TP + 255) / 256), 256>>>(x, w1q, w1s, w1z, w3q, w3s, w3z, w2q, w2s, w2z);

    // h = silu(x w1^T) * (x w3^T), fused: N = 2*IDIM interleaved -> h [TOK, IDIM]
    k_gemm_tma<0><<<dim3(TOK / 128, (2 * IDIM) / 128), 256, SMEM>>>(tmX, tmW13, p_h, 2 * IDIM, HID);

    // out = h * w2^T (x HSC) -> fp32 [TOK, HID]
    k_gemm_tma<1><<<dim3(TOK / 128, HID / 128), 256, SMEM>>>(tmH, tmW2, out, HID, IDIM);
}

// round 15
// speedup vs baseline: 1.2479x; 1.0002x over previous
#include <cuda_runtime.h>
#include <cuda.h>
#include <cuda_fp16.h>
#include <cstdint>
#include <cstddef>
#include <math.h>

#define HID   4096
#define IDIM  14336
#define TOK   4096
#define GS    64
#define HSC   512.0f

// ---------------- scratch (static device globals; no allocation) ----------------
__device__ __align__(128) __half d_w13[(size_t)2 * IDIM * HID];  // [2*IDIM, HID], rows interleaved: 2i=w1_i, 2i+1=w3_i
__device__ __align__(128) __half d_w2h[(size_t)HID * IDIM];      // [HID, IDIM]
__device__ __align__(128) __half d_xh [(size_t)TOK * HID];       // [TOK, HID]
__device__ __align__(128) __half d_h  [(size_t)TOK * IDIM];      // [TOK, IDIM], scaled 1/HSC

// ---------------- prep1: dequant w13 + cvt x (needed by GEMM1) ----------------
__global__ void k_prep1(const float* __restrict__ x,
                        const int* __restrict__ q1, const float* __restrict__ s1, const float* __restrict__ z1,
                        const int* __restrict__ q3, const float* __restrict__ s3, const float* __restrict__ z3) {
    const int T13 = (int)((size_t)IDIM * HID / 4);
    int idx = blockIdx.x * blockDim.x + threadIdx.x;

    if (idx < T13) {
        int e   = idx * 4;
        int row = e >> 12;
        int col = e & (HID - 1);
        int gi  = row * (HID / GS) + (col >> 6);

        int4 q = ((const int4*)q1)[idx];
        float sc = s1[gi], zp = z1[gi];
        __half2* o = (__half2*)(d_w13 + (size_t)(2 * row) * HID + col);       // w1 -> even rows
        o[0] = __floats2half2_rn(((float)q.x - zp) * sc, ((float)q.y - zp) * sc);
        o[1] = __floats2half2_rn(((float)q.z - zp) * sc, ((float)q.w - zp) * sc);

        q = ((const int4*)q3)[idx];
        sc = s3[gi]; zp = z3[gi];
        o = (__half2*)(d_w13 + (size_t)(2 * row + 1) * HID + col);            // w3 -> odd rows
        o[0] = __floats2half2_rn(((float)q.x - zp) * sc, ((float)q.y - zp) * sc);
        o[1] = __floats2half2_rn(((float)q.z - zp) * sc, ((float)q.w - zp) * sc);
    } else {
        idx -= T13;
        if (idx < TOK * HID / 4) {
            float4 v = ((const float4*)x)[idx];
            __half2* o = (__half2*)(d_xh + (size_t)idx * 4);
            o[0] = __floats2half2_rn(v.x, v.y);
            o[1] = __floats2half2_rn(v.z, v.w);
        }
    }
}

// ---------------- prep2: dequant w2 (needed only by GEMM2; overlaps GEMM1) ----------------
__global__ void k_prep2(const int* __restrict__ qw, const float* __restrict__ s, const float* __restrict__ z) {
    int idx = blockIdx.x * blockDim.x + threadIdx.x;
    const int total = (int)((size_t)HID * IDIM / 4);
    if (idx >= total) return;
    int e   = idx * 4;
    int row = e / IDIM;
    int col = e - row * IDIM;
    int gi  = row * (IDIM / GS) + (col >> 6);

    int4 q = ((const int4*)qw)[idx];
    float sc = s[gi], zp = z[gi];
    __half2* o = (__half2*)(d_w2h + (size_t)e);
    o[0] = __floats2half2_rn(((float)q.x - zp) * sc, ((float)q.y - zp) * sc);
    o[1] = __floats2half2_rn(((float)q.z - zp) * sc, ((float)q.w - zp) * sc);
}

// ---------------- PTX helpers ----------------
__device__ __forceinline__ uint32_t s2u(const void* p) {
    uint32_t a;
    asm("{ .reg .u64 t; cvta.to.shared.u64 t, %1; cvt.u32.u64 %0, t; }" : "=r"(a) : "l"(p));
    return a;
}
__device__ __forceinline__ void mbar_init(uint32_t mbar, uint32_t cnt) {
    asm volatile("mbarrier.init.shared.b64 [%0], %1;\n" :: "r"(mbar), "r"(cnt) : "memory");
}
__device__ __forceinline__ void mbar_wait(uint32_t mbar, uint32_t parity) {
    uint32_t done;
    do {
        asm volatile("{\n\t.reg .pred p;\n\t"
                     "mbarrier.try_wait.parity.acquire.cta.shared::cta.b64 p, [%1], %2, 0x989680;\n\t"
                     "selp.b32 %0, 1, 0, p;\n\t}"
                     : "=r"(done) : "r"(mbar), "r"(parity) : "memory");
    } while (!done);
}
__device__ __forceinline__ void mbar_wait_relaxed(uint32_t mbar, uint32_t parity) {
    uint32_t done;
    do {
        asm volatile("{\n\t.reg .pred p;\n\t"
                     "mbarrier.try_wait.parity.relaxed.cta.shared::cta.b64 p, [%1], %2, 0x989680;\n\t"
                     "selp.b32 %0, 1, 0, p;\n\t}"
                     : "=r"(done) : "r"(mbar), "r"(parity) : "memory");
    } while (!done);
}
__device__ __forceinline__ void mbar_arrive(uint32_t mbar) {
    asm volatile("mbarrier.arrive.shared.b64 _, [%0];" :: "r"(mbar) : "memory");
}
__device__ __forceinline__ void mbar_expect_tx(uint32_t mbar, uint32_t bytes) {
    asm volatile("mbarrier.arrive.expect_tx.shared.b64 _, [%0], %1;" :: "r"(mbar), "r"(bytes) : "memory");
}
__device__ __forceinline__ void tma_load_2d(uint32_t dst, const CUtensorMap* tm, int x, int y, uint32_t mbar) {
    asm volatile("cp.async.bulk.tensor.2d.shared::cta.global.tile.mbarrier::complete_tx::bytes "
                 "[%0], [%1, {%2, %3}], [%4];"
                 :: "r"(dst), "l"(tm), "r"(x), "r"(y), "r"(mbar) : "memory");
}
__device__ __forceinline__ void ldsm4(uint32_t* r, uint32_t addr) {
    asm volatile("ldmatrix.sync.aligned.m8n8.x4.shared.b16 {%0,%1,%2,%3}, [%4];"
                 : "=r"(r[0]), "=r"(r[1]), "=r"(r[2]), "=r"(r[3]) : "r"(addr));
}
__device__ __forceinline__ void mma_16816(float* c, const uint32_t* a, const uint32_t* b) {
    asm volatile(
        "mma.sync.aligned.m16n8k16.row.col.f32.f16.f16.f32 "
        "{%0,%1,%2,%3}, {%4,%5,%6,%7}, {%8,%9}, {%0,%1,%2,%3};\n"
        : "+f"(c[0]), "+f"(c[1]), "+f"(c[2]), "+f"(c[3])
        : "r"(a[0]), "r"(a[1]), "r"(a[2]), "r"(a[3]), "r"(b[0]), "r"(b[1]));
}
__device__ __forceinline__ void sts16(uint32_t addr, uint16_t v) {
    asm volatile("st.shared.u16 [%0], %1;" :: "r"(addr), "h"(v) : "memory");
}
__device__ __forceinline__ void lds128(uint32_t addr, uint32_t* v) {
    asm volatile("ld.shared.v4.u32 {%0,%1,%2,%3}, [%4];"
                 : "=r"(v[0]), "=r"(v[1]), "=r"(v[2]), "=r"(v[3]) : "r"(addr));
}

// ---------------- fp16 mma.sync NT GEMM, TMA + mbarrier pipeline ----------------
// 128x128x64 CTA k-tile, 8 warps (2x4) of 64x32 warp tiles, 3-stage TMA ring,
// SW128-swizzled SMEM, fragment double-buffering, early stage release,
// no mainloop __syncthreads.  (R10 structure — best measured.)
// C[M,N] = A[M,K] * B[N,K]^T ; A,B fp16 row-major K-contiguous.
// EPI=0: SwiGLU-fused epilogue, smem-staged coalesced fp16 stores of h[M, N/2] (1/HSC).
// EPI=1: fp32 output scaled by HSC, direct stores.
template <int EPI>
__global__ void __launch_bounds__(256, 2) k_gemm_tma(const __grid_constant__ CUtensorMap tmA,
                                                     const __grid_constant__ CUtensorMap tmB,
                                                     void* __restrict__ Cv,
                                                     int N, int K) {
    constexpr int BM = 128, BN = 128, BK = 64;
    constexpr int ROW_B = 128;                      // 64 halves, SW128 swizzled
    constexpr int A_BYTES = BM * ROW_B;             // 16384
    constexpr int STAGE_BYTES = (BM + BN) * ROW_B;  // 32768
    constexpr uint32_t STAGE_TX = STAGE_BYTES;
    constexpr int EPI_STRIDE_H = 72;                // padded half-stride for epilogue staging

    extern __shared__ __align__(128) char smem[];
    const uint32_t raw = s2u(smem);
    const uint32_t sbase = (raw + 1023u) & ~1023u;  // SW128 atoms need 1024B alignment
    const uint32_t mb = sbase + 3 * STAGE_BYTES;    // full[s]=mb+16s, empty[s]=mb+16s+8

    const int tid  = threadIdx.x;
    const int warp = tid >> 5, lane = tid & 31;
    const int wm = warp >> 2, wn = warp & 3;        // 2x4 warp grid, warp tile 64x32
    const int bm = blockIdx.x * BM, bn = blockIdx.y * BN;
    const int KT = K / BK;

    if (tid == 0) {
        asm volatile("prefetch.tensormap [%0];" :: "l"(&tmA));
        asm volatile("prefetch.tensormap [%0];" :: "l"(&tmB));
        for (int s = 0; s < 3; s++) {
            mbar_init(mb + s * 16, 1);      // full: expect_tx arrival
            mbar_init(mb + s * 16 + 8, 8);  // empty: 8 warp arrivals
        }
    }
    __syncthreads();

    float acc[4][4][4];
#pragma unroll
    for (int a = 0; a < 4; a++)
#pragma unroll
        for (int b = 0; b < 4; b++)
#pragma unroll
            for (int c = 0; c < 4; c++) acc[a][b][c] = 0.0f;

    // producer cursor (tid 0 only): produce data index i into stage i%3
    int pst = 0, pph = 1;
    auto produce = [&](int i) {
        mbar_wait_relaxed(mb + pst * 16 + 8, pph);  // wait empty (async-proxy writes follow)
        mbar_expect_tx(mb + pst * 16, STAGE_TX);
        const uint32_t st = sbase + pst * STAGE_BYTES;
        tma_load_2d(st,           &tmA, i * BK, bm, mb + pst * 16);
        tma_load_2d(st + A_BYTES, &tmB, i * BK, bn, mb + pst * 16);
        if (++pst == 3) { pst = 0; pph ^= 1; }
    };
    if (tid == 0) { produce(0); produce(1); }

    // consumer ldmatrix addressing (SW128: phys_chunk = chunk ^ (row & 7))
    const int xr = lane & 7;
    const int a_hi = lane >> 4;                     // 0/1 -> +8 halves in K
    const int b_hi = (lane >> 3) & 1;
    const uint32_t a_row = (uint32_t)(wm * 64 + (lane & 15)) * ROW_B;
    const uint32_t b_row = (uint32_t)A_BYTES +
                           (uint32_t)(wn * 32 + (lane & 7) + ((lane >> 4) & 1) * 8) * ROW_B;

    uint32_t af[2][4][4], bf[2][4][2];
    auto load_frags = [&](int buf, uint32_t st, int ks) {
        const uint32_t qa = (uint32_t)(((2 * ks + a_hi) ^ xr) * 16);
        const uint32_t a0 = st + a_row + qa;
#pragma unroll
        for (int mi = 0; mi < 4; mi++)
            ldsm4(af[buf][mi], a0 + mi * (16 * ROW_B));
        const uint32_t qb = (uint32_t)(((2 * ks + b_hi) ^ xr) * 16);
        const uint32_t b0 = st + b_row + qb;
        ldsm4(&bf[buf][0][0], b0);
        ldsm4(&bf[buf][2][0], b0 + 16 * ROW_B);
    };
    auto do_mma = [&](int buf) {
#pragma unroll
        for (int mi = 0; mi < 4; mi++)
#pragma unroll
            for (int ni = 0; ni < 4; ni++)
                mma_16816(acc[mi][ni], af[buf][mi], bf[buf][ni]);
    };

    // consumer full-wait cursor
    int ws = 0, wph = 0;
    mbar_wait(mb + ws * 16, wph);                   // stage 0 full
    if (++ws == 3) { ws = 0; wph ^= 1; }
    load_frags(0, sbase, 0);

#pragma unroll 1
    for (int kt = 0; kt < KT; kt++) {
        const int s = kt % 3;
        const uint32_t st = sbase + s * STAGE_BYTES;
        load_frags(1, st, 1);
        do_mma(0);                                  // ks0
        if (tid == 0 && kt + 2 < KT) produce(kt + 2);
        load_frags(0, st, 2);
        do_mma(1);                                  // ks1
        load_frags(1, st, 3);                       // LAST read of stage s (per-warp smem order)
        if (lane == 0) mbar_arrive(mb + s * 16 + 8);  // EARLY release of stage s
        do_mma(0);                                  // ks2
        if (kt + 1 < KT) {
            mbar_wait(mb + ws * 16, wph);           // next stage full
            if (++ws == 3) { ws = 0; wph ^= 1; }
            load_frags(0, sbase + ((kt + 1) % 3) * STAGE_BYTES, 0);
        }
        do_mma(1);                                  // ks3
    }

    // ---------------- epilogue ----------------
    if constexpr (EPI == 0) {
        // SwiGLU + smem-staged coalesced stores.
        __syncthreads();                            // all warps done with stage smem
        const uint32_t eb = sbase;                  // 128 x 72 halves staging buffer
#pragma unroll
        for (int mi = 0; mi < 4; mi++) {
#pragma unroll
            for (int ni = 0; ni < 4; ni++) {
                const int r0 = wm * 64 + mi * 16 + (lane >> 2);     // local row 0..127
                const int c  = wn * 16 + ni * 4 + (lane & 3);       // local half-col 0..63
                float g0 = acc[mi][ni][0], u0 = acc[mi][ni][1];
                float g1 = acc[mi][ni][2], u1 = acc[mi][ni][3];
                float h0 = __fdividef(g0, 1.0f + __expf(-g0)) * u0 * (1.0f / HSC);
                float h1 = __fdividef(g1, 1.0f + __expf(-g1)) * u1 * (1.0f / HSC);
                sts16(eb + (uint32_t)(r0 * EPI_STRIDE_H + c) * 2,
                      __half_as_ushort(__float2half_rn(h0)));
                sts16(eb + (uint32_t)((r0 + 8) * EPI_STRIDE_H + c) * 2,
                      __half_as_ushort(__float2half_rn(h1)));
            }
        }
        __syncthreads();
        // coalesced copy: 128 rows x 64 halves (128B/row), 8 x 16B chunks per row
        __half* C = (__half*)Cv;
        const int No = N >> 1;
        const int rr = tid >> 3;                    // row 0..31 (+32 per iter)
        const int ch = tid & 7;                     // 16B chunk
#pragma unroll
        for (int it = 0; it < 4; it++) {
            const int r = rr + it * 32;
            uint32_t v[4];
            lds128(eb + (uint32_t)(r * EPI_STRIDE_H + ch * 8) * 2, v);
            *(uint4*)(C + (size_t)(bm + r) * No + (bn >> 1) + ch * 8) =
                make_uint4(v[0], v[1], v[2], v[3]);
        }
    } else {
#pragma unroll
        for (int mi = 0; mi < 4; mi++) {
#pragma unroll
            for (int ni = 0; ni < 4; ni++) {
                const int row = bm + wm * 64 + mi * 16 + (lane >> 2);
                const int col = bn + wn * 32 + ni * 8 + (lane & 3) * 2;
                float* C = (float*)Cv;
                float2 v0 = make_float2(acc[mi][ni][0] * HSC, acc[mi][ni][1] * HSC);
                float2 v1 = make_float2(acc[mi][ni][2] * HSC, acc[mi][ni][3] * HSC);
                *(float2*)(C + (size_t)row * N + col)       = v0;
                *(float2*)(C + (size_t)(row + 8) * N + col) = v1;
            }
        }
    }
}

// ---------------- host: tensormap creation via driver entry point ----------------
typedef CUresult (CUDAAPI *PFN_TMEncode)(
    CUtensorMap*, CUtensorMapDataType, cuuint32_t, void*,
    const cuuint64_t*, const cuuint64_t*, const cuuint32_t*, const cuuint32_t*,
    CUtensorMapInterleave, CUtensorMapSwizzle, CUtensorMapL2promotion, CUtensorMapFloatOOBfill);

static void make_map_f16(PFN_TMEncode enc, CUtensorMap* tm, void* ptr,
                         unsigned long long inner, unsigned long long rows) {
    cuuint64_t dims[2]    = {inner, rows};
    cuuint64_t strides[1] = {inner * 2};          // bytes
    cuuint32_t box[2]     = {64, 128};            // 128B inner (SW128 limit), 128 rows
    cuuint32_t es[2]      = {1, 1};
    enc(tm, CU_TENSOR_MAP_DATA_TYPE_FLOAT16, 2, ptr, dims, strides, box, es,
        CU_TENSOR_MAP_INTERLEAVE_NONE, CU_TENSOR_MAP_SWIZZLE_128B,
        CU_TENSOR_MAP_L2_PROMOTION_L2_128B, CU_TENSOR_MAP_FLOAT_OOB_FILL_NONE);
}

// ---------------- launch ----------------
extern "C" void kernel_launch(void* const* d_in, const int* in_sizes, int n_in,
                              void* d_out, int out_size) {
    const float* x   = (const float*)d_in[0];
    const int*   w1q = (const int*)  d_in[1];
    const float* w1s = (const float*)d_in[2];
    const float* w1z = (const float*)d_in[3];
    const int*   w3q = (const int*)  d_in[4];
    const float* w3s = (const float*)d_in[5];
    const float* w3z = (const float*)d_in[6];
    const int*   w2q = (const int*)  d_in[7];
    const float* w2s = (const float*)d_in[8];
    const float* w2z = (const float*)d_in[9];
    float* out = (float*)d_out;

    __half *p_w13, *p_w2h, *p_xh, *p_h;
    cudaGetSymbolAddress((void**)&p_w13, d_w13);
    cudaGetSymbolAddress((void**)&p_w2h, d_w2h);
    cudaGetSymbolAddress((void**)&p_xh,  d_xh);
    cudaGetSymbolAddress((void**)&p_h,   d_h);

    void* fn = nullptr;
    cudaDriverEntryPointQueryResult qres;
    cudaGetDriverEntryPoint("cuTensorMapEncodeTiled", &fn, cudaEnableDefault, &qres);
    PFN_TMEncode enc = (PFN_TMEncode)fn;

    CUtensorMap tmX, tmW13, tmH, tmW2;
    make_map_f16(enc, &tmX,   p_xh,  HID,  TOK);        // A of GEMM1
    make_map_f16(enc, &tmW13, p_w13, HID,  2 * IDIM);   // B of GEMM1
    make_map_f16(enc, &tmH,   p_h,   IDIM, TOK);        // A of GEMM2
    make_map_f16(enc, &tmW2,  p_w2h, IDIM, HID);        // B of GEMM2

    const int SMEM = 1024 + 3 * 32768 + 128;   // align slack + 3 stages + mbarriers
    cudaFuncSetAttribute(k_gemm_tma<0>, cudaFuncAttributeMaxDynamicSharedMemorySize, SMEM);
    cudaFuncSetAttribute(k_gemm_tma<1>, cudaFuncAttributeMaxDynamicSharedMemorySize, SMEM);

    // side stream + fork/join events, created once on the first (non-capture) call
    static cudaStream_t s2 = nullptr;
    static cudaEvent_t ev_fork = nullptr, ev_join = nullptr;
    if (s2 == nullptr) {
        cudaStreamCreateWithFlags(&s2, cudaStreamNonBlocking);
        cudaEventCreateWithFlags(&ev_fork, cudaEventDisableTiming);
        cudaEventCreateWithFlags(&ev_join, cudaEventDisableTiming);
    }

    const long T13 = (long)IDIM * HID / 4;
    const long T2  = (long)HID * IDIM / 4;
    const long TX  = (long)TOK * HID / 4;

    // fork: w2 dequant on side stream, overlapping prep1 + GEMM1
    cudaEventRecord(ev_fork, 0);
    cudaStreamWaitEvent(s2, ev_fork, 0);
    k_prep2<<<(int)((T2 + 255) / 256), 256, 0, s2>>>(w2q, w2s, w2z);
    cudaEventRecord(ev_join, s2);

    // main stream: prep1 (w13 + x) then GEMM1
    k_prep1<<<(int)((T13 + TX + 255) / 256), 256>>>(x, w1q, w1s, w1z, w3q, w3s, w3z);

    // h = silu(x w1^T) * (x w3^T), fused: N = 2*IDIM interleaved -> h [TOK, IDIM]
    k_gemm_tma<0><<<dim3(TOK / 128, (2 * IDIM) / 128), 256, SMEM>>>(tmX, tmW13, p_h, 2 * IDIM, HID);

    // join: GEMM2 needs w2h
    cudaStreamWaitEvent(0, ev_join, 0);

    // out = h * w2^T (x HSC) -> fp32 [TOK, HID]
    k_gemm_tma<1><<<dim3(TOK / 128, HID / 128), 256, SMEM>>>(tmH, tmW2, out, HID, IDIM);
}